// round 11
// baseline (speedup 1.0000x reference)
#include <cuda_runtime.h>

#define WID 512
#define HEI 512
#define NPIX (WID*HEI)
#define RAD 10
#define KS 21
#define TPB 256
#define TSX 32
#define TSY 16
#define TINX 52
#define TINY 36
#define SINP 53                 // padded input tile stride (u64 units; odd -> CF column access)
#define SHP  33                 // padded H-buffer stride (odd -> CF column access)
#define NTX (WID/TSX)           // 16
#define NTY (HEI/TSY)           // 32
#define NTILES (NTX*NTY)        // 512
#define NELEM (TINY*SINP)       // 1908

// smem layout (bytes) — overlap-packed per phase
#define OFF_IN0   0                       // u64[NELEM] = 15264
#define OFF_GRAY  15264                   // float[NELEM] = 7632  (PhaseA)
#define OFF_INB   15264                   // u64[NELEM] (PhaseB second input)
#define OFF_AH0   22896                   // H buffers: u64[TINY*SHP] = 9504
#define OFF_AH1   32400
#define OFF_AH2   41904
#define OFF_BH0   30528
#define OFF_BH1   40032
#define SMEM_BYTES 51408

typedef unsigned long long u64;

// ---------------- compile-time weights ----------------
constexpr double cexp(double x) {
    double y = x / 16.0, s = 1.0, t = 1.0;
    for (int i = 1; i < 40; i++) { t *= y / (double)i; s += t; }
    s = s * s; s = s * s; s = s * s; s = s * s;
    return s;
}
constexpr double wgd(int t) { double d = (double)(t - RAD); return cexp(-d * d / 12.5); }
constexpr double wdd(int t) { double d = (double)(t - RAD); return cexp(-d * d * 9.0 / 200.0); }
constexpr double sumw(int wh) { double s = 0; for (int i = 0; i < KS; i++) s += (wh ? wgd(i) : wdd(i)); return s; }
constexpr double pref(int wh, int n) { double s = 0; for (int i = 0; i < n; i++) s += (wh ? wgd(i) : wdd(i)); return s; }

constexpr float SD_F    = (float)sumw(0);
constexpr float SG_F    = (float)sumw(1);
constexpr float SDINV_F = (float)(1.0 / (sumw(0) * sumw(0)));

#define TAPLIST(F) F(0) F(1) F(2) F(3) F(4) F(5) F(6) F(7) F(8) F(9) F(10) \
                   F(11) F(12) F(13) F(14) F(15) F(16) F(17) F(18) F(19) F(20)
#define DWG(i) constexpr float WG_##i = (float)wgd(i);
#define DWD(i) constexpr float WD_##i = (float)wdd(i);
TAPLIST(DWG)
TAPLIST(DWD)

__device__ __forceinline__ float wG(int t) {
    switch (t) {
#define CWG(i) case i: return WG_##i;
        TAPLIST(CWG)
#undef CWG
    }
    return 0.f;
}
__device__ __forceinline__ float wD(int t) {
    switch (t) {
#define CWD(i) case i: return WD_##i;
        TAPLIST(CWD)
#undef CWD
    }
    return 0.f;
}

__constant__ float c_pD[11] = {
    (float)pref(0,0),(float)pref(0,1),(float)pref(0,2),(float)pref(0,3),(float)pref(0,4),
    (float)pref(0,5),(float)pref(0,6),(float)pref(0,7),(float)pref(0,8),(float)pref(0,9),
    (float)pref(0,10)
};
__constant__ float c_pG[11] = {
    (float)pref(1,0),(float)pref(1,1),(float)pref(1,2),(float)pref(1,3),(float)pref(1,4),
    (float)pref(1,5),(float)pref(1,6),(float)pref(1,7),(float)pref(1,8),(float)pref(1,9),
    (float)pref(1,10)
};

__device__ __forceinline__ float hsD(int x) {
    float s = SD_F;
    if (x < RAD) s -= c_pD[RAD - x];
    if (x > WID - 1 - RAD) s -= c_pD[x - (WID - 1 - RAD)];
    return s;
}
__device__ __forceinline__ float hsG(int x) {
    float s = SG_F;
    if (x < RAD) s -= c_pG[RAD - x];
    if (x > WID - 1 - RAD) s -= c_pG[x - (WID - 1 - RAD)];
    return s;
}

// ---------------- packed f32x2 helpers ----------------
__device__ __forceinline__ u64 pk2(float x, float y) {
    u64 r; asm("mov.b64 %0,{%1,%2};" : "=l"(r) : "f"(x), "f"(y)); return r;
}
__device__ __forceinline__ float2 up2(u64 v) {
    float2 o; asm("mov.b64 {%0,%1},%2;" : "=f"(o.x), "=f"(o.y) : "l"(v)); return o;
}
__device__ __forceinline__ void fma2(u64& d, u64 a, u64 b) {
    asm("fma.rn.f32x2 %0,%1,%2,%0;" : "+l"(d) : "l"(a), "l"(b));
}
__device__ __forceinline__ u64 mul2(u64 a, u64 b) {
    u64 r; asm("mul.rn.f32x2 %0,%1,%2;" : "=l"(r) : "l"(a), "l"(b)); return r;
}
__device__ __forceinline__ u64 wpc(float w) {   // (w,w) pair; constant-folds after unroll
    unsigned u = __float_as_uint(w);
    return ((u64)u << 32) | (u64)u;
}

// ---------------- static device planes ----------------
__device__ float g_gray[NPIX], g_ibn[NPIX], g_spc[NPIX];
__device__ u64 g_miv[NPIX];                  // packed (mean_I, inv_var)
__device__ u64 g_ab1[NPIX];
__device__ u64 g_Qxy[NPIX], g_Qzw[NPIX];
__device__ u64 g_a0[NPIX], g_a1p[NPIX], g_b0[NPIX], g_b1p[NPIX], g_sp0[NPIX], g_sp1[NPIX];

// ---------------- grid barrier ----------------
__device__ unsigned g_count = 0;
__device__ unsigned g_gen   = 0;

__device__ __forceinline__ unsigned gridbar(unsigned gen, int nb) {
    unsigned next = gen + 1;
    __threadfence();
    __syncthreads();
    if (threadIdx.x == 0) {
        if (atomicAdd(&g_count, 1) == (unsigned)(nb - 1)) {
            g_count = 0;
            __threadfence();
            atomicExch(&g_gen, next);
        } else {
            volatile unsigned* ph = &g_gen;
            while (*ph != next) { __nanosleep(40); }
        }
    }
    __syncthreads();
    __threadfence();
    return next;
}

__device__ __forceinline__ float4 softmax4(float4 z) {
    float m = fmaxf(fmaxf(z.x, z.y), fmaxf(z.z, z.w));
    float ex = __expf(z.x - m), ey = __expf(z.y - m);
    float ez = __expf(z.z - m), ew = __expf(z.w - m);
    float inv = 1.f / (ex + ey + ez + ew);
    return make_float4(ex * inv, ey * inv, ez * inv, ew * inv);
}

// ---- division-free tile loaders: warp w owns rows w, w+8, ... ----
__device__ __forceinline__ void load_tile(u64* dst, const u64* src,
                                          int X0, int Y0, int wid, int lane) {
    for (int r = wid; r < TINY; r += 8) {
        int gy = Y0 + r - RAD;
        bool yok = (unsigned)gy < HEI;
        int gx = X0 + lane - RAD;
        u64 v0 = 0ULL;
        if (yok && (unsigned)gx < WID) v0 = src[gy * WID + gx];
        dst[r * SINP + lane] = v0;
        if (lane < TINX - 32) {
            int gx1 = gx + 32;
            u64 v1 = 0ULL;
            if (yok && (unsigned)gx1 < WID) v1 = src[gy * WID + gx1];
            dst[r * SINP + lane + 32] = v1;
        }
    }
}
__device__ __forceinline__ void load_tile_f(float* dst, const float* src,
                                            int X0, int Y0, int wid, int lane) {
    for (int r = wid; r < TINY; r += 8) {
        int gy = Y0 + r - RAD;
        bool yok = (unsigned)gy < HEI;
        int gx = X0 + lane - RAD;
        float v0 = 0.f;
        if (yok && (unsigned)gx < WID) v0 = src[gy * WID + gx];
        dst[r * SINP + lane] = v0;
        if (lane < TINX - 32) {
            int gx1 = gx + 32;
            float v1 = 0.f;
            if (yok && (unsigned)gx1 < WID) v1 = src[gy * WID + gx1];
            dst[r * SINP + lane + 32] = v1;
        }
    }
}

// H geometry, width-4 chunks (9 tasks; used by PhaseA with 3 quantities)
__device__ __forceinline__ void htask_geom4(int task, int lane, int& row, int& xb) {
    if (task < 8) { row = lane;              xb = task * 4; }
    else          { row = 32 + (lane >> 3);  xb = (lane & 7) * 4; }
}
// H geometry, width-8 chunks (5 tasks; used by Pre and PhaseB)
__device__ __forceinline__ bool htask_geom8(int task, int lane, int& row, int& xb) {
    if (task < 4) { row = lane;             xb = task * 8;        return true; }
    row = 32 + (lane >> 2); xb = (lane & 3) * 8; return lane < 16;
}

// ---------------- the persistent kernel ----------------
__global__ void __launch_bounds__(TPB, 4)
k_crf(const float* __restrict__ img, const float4* __restrict__ unary,
      float4* __restrict__ dout, int nb) {
    extern __shared__ char dsm[];
    u64*   sIn  = (u64*)(dsm + OFF_IN0);
    float* sg   = (float*)(dsm + OFF_GRAY);
    u64*   sInB = (u64*)(dsm + OFF_INB);
    u64*   aH0  = (u64*)(dsm + OFF_AH0);
    u64*   aH1  = (u64*)(dsm + OFF_AH1);
    u64*   aH2  = (u64*)(dsm + OFF_AH2);
    u64*   bH0  = (u64*)(dsm + OFF_BH0);
    u64*   bH1  = (u64*)(dsm + OFF_BH1);

    const int tid  = threadIdx.x;
    const int wid  = tid >> 5;
    const int lane = tid & 31;
    const int gid  = blockIdx.x * TPB + tid;
    const int T    = nb * TPB;

    unsigned gen;
    {
        __shared__ unsigned sgen;
        if (tid == 0) sgen = *(volatile unsigned*)&g_gen;
        __syncthreads();
        gen = sgen;
    }

    // ---- P0: grayscale + Q0 = softmax(-unary) ----
    for (int i = gid; i < NPIX; i += T) {
        float r = img[3 * i], gg = img[3 * i + 1], b = img[3 * i + 2];
        g_gray[i] = 0.2989f * r + 0.5870f * gg + 0.1140f * b;
        float4 u = unary[i];
        float4 q = softmax4(make_float4(-u.x, -u.y, -u.z, -u.w));
        g_Qxy[i] = pk2(q.x, q.y);
        g_Qzw[i] = pk2(q.z, q.w);
    }
    gen = gridbar(gen, nb);

    // ---- PreA: conv2D of (gray, gray^2) -> (mI,iv), (a1,b1) ----
    for (int t = blockIdx.x; t < NTILES; t += nb) {
        int X0 = (t & (NTX - 1)) * TSX, Y0 = (t >> 4) * TSY;
        // fill (g, g^2) tile, row-mapped
        for (int r = wid; r < TINY; r += 8) {
            int gy = Y0 + r - RAD;
            bool yok = (unsigned)gy < HEI;
            int gx = X0 + lane - RAD;
            u64 v0 = 0ULL;
            if (yok && (unsigned)gx < WID) { float gv = g_gray[gy * WID + gx]; v0 = pk2(gv, gv * gv); }
            sIn[r * SINP + lane] = v0;
            if (lane < TINX - 32) {
                int gx1 = gx + 32;
                u64 v1 = 0ULL;
                if (yok && (unsigned)gx1 < WID) { float gv = g_gray[gy * WID + gx1]; v1 = pk2(gv, gv * gv); }
                sIn[r * SINP + lane + 32] = v1;
            }
        }
        __syncthreads();
        // H, width 8, 5 tasks
        if (wid < 5) {
            int row, xb;
            if (htask_geom8(wid, lane, row, xb)) {
                u64 a[8] = {0,0,0,0,0,0,0,0};
                const u64* rw = sIn + row * SINP + xb;
#pragma unroll
                for (int tt = 0; tt < 28; tt++) {
                    u64 v = rw[tt];
#pragma unroll
                    for (int m = 0; m < 8; m++) {
                        int w = tt - m;
                        if (w >= 0 && w < KS) fma2(a[m], v, wpc(wD(w)));
                    }
                }
#pragma unroll
                for (int m = 0; m < 8; m++) aH0[row * SHP + xb + m] = a[m];
            }
        }
        __syncthreads();
        // V, 8 rows/thread, 2 warps
        if (wid < 2) {
            int py0 = wid * 8;
            u64 A[8] = {0,0,0,0,0,0,0,0};
#pragma unroll
            for (int j = 0; j < 28; j++) {
                u64 v = aH0[(py0 + j) * SHP + lane];
#pragma unroll
                for (int m = 0; m < 8; m++) {
                    int w = j - m;
                    if (w >= 0 && w < KS) fma2(A[m], v, wpc(wD(w)));
                }
            }
            float hdx = hsD(X0 + lane);
#pragma unroll
            for (int m = 0; m < 8; m++) {
                int py = py0 + m, gy = Y0 + py, idx = gy * WID + X0 + lane;
                float2 c = up2(A[m]);
                float g = up2(sIn[(py + RAD) * SINP + lane + RAD]).x;
                float mI  = (c.x - g) * SDINV_F;
                float mII = (c.y - g * g) * SDINV_F;
                float mp1 = (hdx * hsD(gy) - 1.f) * SDINV_F;
                float var = mII - mI * mI;
                float iv  = 1.f / (var + 1e-4f);
                float a1  = mI * (1.f - mp1) * iv;
                float b1  = mp1 - a1 * mI;
                g_miv[idx] = pk2(mI, iv);
                g_ab1[idx] = pk2(a1, b1);
            }
        }
        __syncthreads();
    }
    gen = gridbar(gen, nb);

    // ---- PreB: conv2D of (a1,b1) -> ibn, spc ----
    for (int t = blockIdx.x; t < NTILES; t += nb) {
        int X0 = (t & (NTX - 1)) * TSX, Y0 = (t >> 4) * TSY;
        load_tile(sIn, g_ab1, X0, Y0, wid, lane);
        __syncthreads();
        if (wid < 5) {
            int row, xb;
            if (htask_geom8(wid, lane, row, xb)) {
                u64 a[8] = {0,0,0,0,0,0,0,0};
                const u64* rw = sIn + row * SINP + xb;
#pragma unroll
                for (int tt = 0; tt < 28; tt++) {
                    u64 v = rw[tt];
#pragma unroll
                    for (int m = 0; m < 8; m++) {
                        int w = tt - m;
                        if (w >= 0 && w < KS) fma2(a[m], v, wpc(wD(w)));
                    }
                }
#pragma unroll
                for (int m = 0; m < 8; m++) aH0[row * SHP + xb + m] = a[m];
            }
        }
        __syncthreads();
        if (wid < 2) {
            int py0 = wid * 8;
            u64 A[8] = {0,0,0,0,0,0,0,0};
#pragma unroll
            for (int j = 0; j < 28; j++) {
                u64 v = aH0[(py0 + j) * SHP + lane];
#pragma unroll
                for (int m = 0; m < 8; m++) {
                    int w = j - m;
                    if (w >= 0 && w < KS) fma2(A[m], v, wpc(wD(w)));
                }
            }
            float hgx = hsG(X0 + lane);
#pragma unroll
            for (int m = 0; m < 8; m++) {
                int py = py0 + m, gy = Y0 + py, idx = gy * WID + X0 + lane;
                float2 c  = up2(A[m]);
                float2 ab = up2(sIn[(py + RAD) * SINP + lane + RAD]);
                float g = g_gray[idx];
                float gfa = (c.x - ab.x) * SDINV_F;
                float gfb = (c.y - ab.y) * SDINV_F;
                g_ibn[idx] = 10.f / (gfa * g + gfb);
                g_spc[idx] = 3.f / (hgx * hsG(gy) - 1.f);
            }
        }
        __syncthreads();
    }
    gen = gridbar(gen, nb);

    // ---- 5 mean-field iterations: 2 tiled phases each ----
    for (int it = 0; it < 5; it++) {
        // ===== PhaseA: conv2D(Q)x{G,D} + conv2D(grayQ)xD -> a,b,sp =====
        for (int t = blockIdx.x; t < NTILES; t += nb) {
            int X0 = (t & (NTX - 1)) * TSX, Y0 = (t >> 4) * TSY;
            load_tile_f(sg, g_gray, X0, Y0, wid, lane);
            for (int h = 0; h < 2; h++) {
                load_tile(sIn, h ? g_Qzw : g_Qxy, X0, Y0, wid, lane);
                __syncthreads();
                // H, width 4, 9 tasks (3 quantities: 12 accums)
                for (int task = wid; task < 9; task += 8) {
                    int row, xb; htask_geom4(task, lane, row, xb);
                    u64 aD[4] = {0,0,0,0}, aG[4] = {0,0,0,0}, aI[4] = {0,0,0,0};
                    const u64*  rw = sIn + row * SINP + xb;
                    const float* rg = sg + row * SINP + xb;
#pragma unroll
                    for (int tt = 0; tt < 24; tt++) {
                        u64 v = rw[tt];
                        float gf = rg[tt];
                        u64 wv = mul2(v, pk2(gf, gf));
#pragma unroll
                        for (int m = 0; m < 4; m++) {
                            int w = tt - m;
                            if (w >= 0 && w < KS) {
                                fma2(aD[m], v,  wpc(wD(w)));
                                fma2(aG[m], v,  wpc(wG(w)));
                                fma2(aI[m], wv, wpc(wD(w)));
                            }
                        }
                    }
#pragma unroll
                    for (int m = 0; m < 4; m++) {
                        aH0[row * SHP + xb + m] = aD[m];
                        aH1[row * SHP + xb + m] = aG[m];
                        aH2[row * SHP + xb + m] = aI[m];
                    }
                }
                __syncthreads();
                // V (3 quantities, 4 warps x 4 rows) + elementwise
                if (wid < 4) {
                    int py0 = wid * 4;
                    u64 AD[4] = {0,0,0,0}, AG[4] = {0,0,0,0}, AI[4] = {0,0,0,0};
#pragma unroll
                    for (int j = 0; j < 24; j++) {
                        u64 v0 = aH0[(py0 + j) * SHP + lane];
                        u64 v1 = aH1[(py0 + j) * SHP + lane];
                        u64 v2 = aH2[(py0 + j) * SHP + lane];
#pragma unroll
                        for (int m = 0; m < 4; m++) {
                            int w = j - m;
                            if (w >= 0 && w < KS) {
                                fma2(AD[m], v0, wpc(wD(w)));
                                fma2(AG[m], v1, wpc(wG(w)));
                                fma2(AI[m], v2, wpc(wD(w)));
                            }
                        }
                    }
#pragma unroll
                    for (int m = 0; m < 4; m++) {
                        int py = py0 + m, idx = (Y0 + py) * WID + X0 + lane;
                        float2 q = up2(sIn[(py + RAD) * SINP + lane + RAD]);
                        float g = sg[(py + RAD) * SINP + lane + RAD];
                        float2 ad = up2(AD[m]), ag = up2(AG[m]), ai = up2(AI[m]);
                        float2 mv = up2(g_miv[idx]);
                        float mI = mv.x, iv = mv.y, spc = g_spc[idx];
                        float spx = (ag.x - q.x) * spc,         spy = (ag.y - q.y) * spc;
                        float mpx = (ad.x - q.x) * SDINV_F,     mpy = (ad.y - q.y) * SDINV_F;
                        float mix = (ai.x - g * q.x) * SDINV_F, miy = (ai.y - g * q.y) * SDINV_F;
                        float ax = (mix - mI * mpx) * iv,       ay = (miy - mI * mpy) * iv;
                        float bx = mpx - ax * mI,               by = mpy - ay * mI;
                        if (h == 0) {
                            g_a0[idx]  = pk2(ax, ay);
                            g_b0[idx]  = pk2(bx, by);
                            g_sp0[idx] = pk2(spx, spy);
                        } else {
                            g_a1p[idx] = pk2(ax, ay);
                            g_b1p[idx] = pk2(bx, by);
                            g_sp1[idx] = pk2(spx, spy);
                        }
                    }
                }
                __syncthreads();
            }
        }
        gen = gridbar(gen, nb);

        // ===== PhaseB: conv2D(a,b) + message + softmax -> Q / dout =====
        for (int t = blockIdx.x; t < NTILES; t += nb) {
            int X0 = (t & (NTX - 1)) * TSX, Y0 = (t >> 4) * TSY;
            float z0[8];
            for (int h = 0; h < 2; h++) {
                load_tile(sIn,  h ? g_a1p : g_a0, X0, Y0, wid, lane);
                load_tile(sInB, h ? g_b1p : g_b0, X0, Y0, wid, lane);
                __syncthreads();
                // H, width 8, 5 tasks (2 quantities: 16 accums)
                if (wid < 5) {
                    int row, xb;
                    if (htask_geom8(wid, lane, row, xb)) {
                        u64 aA[8] = {0,0,0,0,0,0,0,0};
                        u64 aB[8] = {0,0,0,0,0,0,0,0};
                        const u64* rwA = sIn  + row * SINP + xb;
                        const u64* rwB = sInB + row * SINP + xb;
#pragma unroll
                        for (int tt = 0; tt < 28; tt++) {
                            u64 vA = rwA[tt], vB = rwB[tt];
#pragma unroll
                            for (int m = 0; m < 8; m++) {
                                int w = tt - m;
                                if (w >= 0 && w < KS) {
                                    fma2(aA[m], vA, wpc(wD(w)));
                                    fma2(aB[m], vB, wpc(wD(w)));
                                }
                            }
                        }
#pragma unroll
                        for (int m = 0; m < 8; m++) {
                            bH0[row * SHP + xb + m] = aA[m];
                            bH1[row * SHP + xb + m] = aB[m];
                        }
                    }
                }
                __syncthreads();
                // V (2 quantities, 4 warps x 4 rows) + message + softmax
                if (wid < 4) {
                    int py0 = wid * 4;
                    u64 AA[4] = {0,0,0,0}, AB[4] = {0,0,0,0};
#pragma unroll
                    for (int j = 0; j < 24; j++) {
                        u64 v0 = bH0[(py0 + j) * SHP + lane];
                        u64 v1 = bH1[(py0 + j) * SHP + lane];
#pragma unroll
                        for (int m = 0; m < 4; m++) {
                            int w = j - m;
                            if (w >= 0 && w < KS) {
                                fma2(AA[m], v0, wpc(wD(w)));
                                fma2(AB[m], v1, wpc(wD(w)));
                            }
                        }
                    }
#pragma unroll
                    for (int m = 0; m < 4; m++) {
                        int py = py0 + m, idx = (Y0 + py) * WID + X0 + lane;
                        float2 ac = up2(sIn [(py + RAD) * SINP + lane + RAD]);
                        float2 bc = up2(sInB[(py + RAD) * SINP + lane + RAD]);
                        float2 aa = up2(AA[m]), ab = up2(AB[m]);
                        float2 sp = up2(h ? g_sp1[idx] : g_sp0[idx]);
                        float ibn = g_ibn[idx], g = g_gray[idx];
                        float2 uu = *((const float2*)unary + 2 * idx + h);
                        float zx = sp.x + ((aa.x - ac.x) * SDINV_F * g
                                         + (ab.x - bc.x) * SDINV_F) * ibn - uu.x;
                        float zy = sp.y + ((aa.y - ac.y) * SDINV_F * g
                                         + (ab.y - bc.y) * SDINV_F) * ibn - uu.y;
                        if (h == 0) {
                            z0[2*m] = zx; z0[2*m+1] = zy;
                        } else {
                            float4 q = softmax4(make_float4(z0[2*m], z0[2*m+1], zx, zy));
                            if (it == 4) {
                                dout[idx] = q;
                            } else {
                                g_Qxy[idx] = pk2(q.x, q.y);
                                g_Qzw[idx] = pk2(q.z, q.w);
                            }
                        }
                    }
                }
                __syncthreads();
            }
        }
        if (it < 4) gen = gridbar(gen, nb);
    }
}

// ---------------- launch ----------------
extern "C" void kernel_launch(void* const* d_in, const int* in_sizes, int n_in,
                              void* d_out, int out_size) {
    const float* unary = nullptr;
    const float* image = nullptr;
    for (int i = 0; i < n_in; i++) {
        if (in_sizes[i] == NPIX * 4) unary = (const float*)d_in[i];
        else if (in_sizes[i] == NPIX * 3) image = (const float*)d_in[i];
    }

    cudaFuncSetAttribute(k_crf, cudaFuncAttributeMaxDynamicSharedMemorySize, SMEM_BYTES);

    int sms = 0, occ = 0;
    cudaDeviceGetAttribute(&sms, cudaDevAttrMultiProcessorCount, 0);
    cudaOccupancyMaxActiveBlocksPerMultiprocessor(&occ, k_crf, TPB, SMEM_BYTES);
    if (sms <= 0) sms = 148;
    if (occ <= 0) occ = 1;
    int nb = sms * occ;
    if (nb > 1024) nb = 1024;

    k_crf<<<nb, TPB, SMEM_BYTES>>>(image, (const float4*)unary, (float4*)d_out, nb);
}

// round 12
// speedup vs baseline: 1.0205x; 1.0205x over previous
#include <cuda_runtime.h>

#define WID 512
#define HEI 512
#define NPIX (WID*HEI)
#define RAD 10
#define KS 21
#define TPB 256
#define TSX 32
#define TSY 16
#define TINX 52
#define TINY 36
#define SINP 53                 // padded input tile stride (u64 units; odd -> CF column access)
#define SHP  33                 // padded H-buffer stride (odd -> CF column access)
#define NTX (WID/TSX)           // 16
#define NTY (HEI/TSY)           // 32
#define NTILES (NTX*NTY)        // 512

// smem layout (bytes) — overlap-packed per phase
#define OFF_IN0   0                       // u64[36*53] = 15264
#define OFF_GRAY  15264                   // float[36*53] = 7632  (PhaseA)
#define OFF_INB   15264                   // u64 tile (PhaseB second input)
#define OFF_AH0   22896                   // H buffers: u64[36*33] = 9504
#define OFF_AH1   32400
#define OFF_AH2   41904
#define OFF_BH0   30528
#define OFF_BH1   40032
#define SMEM_BYTES 51408

typedef unsigned long long u64;

// ---------------- compile-time weights ----------------
constexpr double cexp(double x) {
    double y = x / 16.0, s = 1.0, t = 1.0;
    for (int i = 1; i < 40; i++) { t *= y / (double)i; s += t; }
    s = s * s; s = s * s; s = s * s; s = s * s;
    return s;
}
constexpr double wgd(int t) { double d = (double)(t - RAD); return cexp(-d * d / 12.5); }
constexpr double wdd(int t) { double d = (double)(t - RAD); return cexp(-d * d * 9.0 / 200.0); }
constexpr double sumw(int wh) { double s = 0; for (int i = 0; i < KS; i++) s += (wh ? wgd(i) : wdd(i)); return s; }
constexpr double pref(int wh, int n) { double s = 0; for (int i = 0; i < n; i++) s += (wh ? wgd(i) : wdd(i)); return s; }

constexpr float SD_F    = (float)sumw(0);
constexpr float SG_F    = (float)sumw(1);
constexpr float SDINV_F = (float)(1.0 / (sumw(0) * sumw(0)));

#define TAPLIST(F) F(0) F(1) F(2) F(3) F(4) F(5) F(6) F(7) F(8) F(9) F(10) \
                   F(11) F(12) F(13) F(14) F(15) F(16) F(17) F(18) F(19) F(20)
#define DWG(i) constexpr float WG_##i = (float)wgd(i);
#define DWD(i) constexpr float WD_##i = (float)wdd(i);
TAPLIST(DWG)
TAPLIST(DWD)

__device__ __forceinline__ float wG(int t) {
    switch (t) {
#define CWG(i) case i: return WG_##i;
        TAPLIST(CWG)
#undef CWG
    }
    return 0.f;
}
__device__ __forceinline__ float wD(int t) {
    switch (t) {
#define CWD(i) case i: return WD_##i;
        TAPLIST(CWD)
#undef CWD
    }
    return 0.f;
}

__constant__ float c_pD[11] = {
    (float)pref(0,0),(float)pref(0,1),(float)pref(0,2),(float)pref(0,3),(float)pref(0,4),
    (float)pref(0,5),(float)pref(0,6),(float)pref(0,7),(float)pref(0,8),(float)pref(0,9),
    (float)pref(0,10)
};
__constant__ float c_pG[11] = {
    (float)pref(1,0),(float)pref(1,1),(float)pref(1,2),(float)pref(1,3),(float)pref(1,4),
    (float)pref(1,5),(float)pref(1,6),(float)pref(1,7),(float)pref(1,8),(float)pref(1,9),
    (float)pref(1,10)
};

__device__ __forceinline__ float hsD(int x) {
    float s = SD_F;
    if (x < RAD) s -= c_pD[RAD - x];
    if (x > WID - 1 - RAD) s -= c_pD[x - (WID - 1 - RAD)];
    return s;
}
__device__ __forceinline__ float hsG(int x) {
    float s = SG_F;
    if (x < RAD) s -= c_pG[RAD - x];
    if (x > WID - 1 - RAD) s -= c_pG[x - (WID - 1 - RAD)];
    return s;
}

// ---------------- packed f32x2 helpers ----------------
__device__ __forceinline__ u64 pk2(float x, float y) {
    u64 r; asm("mov.b64 %0,{%1,%2};" : "=l"(r) : "f"(x), "f"(y)); return r;
}
__device__ __forceinline__ float2 up2(u64 v) {
    float2 o; asm("mov.b64 {%0,%1},%2;" : "=f"(o.x), "=f"(o.y) : "l"(v)); return o;
}
__device__ __forceinline__ void fma2(u64& d, u64 a, u64 b) {
    asm("fma.rn.f32x2 %0,%1,%2,%0;" : "+l"(d) : "l"(a), "l"(b));
}
__device__ __forceinline__ u64 mul2(u64 a, u64 b) {
    u64 r; asm("mul.rn.f32x2 %0,%1,%2;" : "=l"(r) : "l"(a), "l"(b)); return r;
}
__device__ __forceinline__ u64 wpc(float w) {   // (w,w) pair; constant-folds after unroll
    unsigned u = __float_as_uint(w);
    return ((u64)u << 32) | (u64)u;
}

// ---------------- static device planes ----------------
__device__ float g_gray[NPIX], g_ibn[NPIX], g_spc[NPIX];
__device__ u64 g_miv[NPIX];                 // packed (mean_I, inv_var)
__device__ u64 g_ab1[NPIX];
__device__ u64 g_Qxy[NPIX], g_Qzw[NPIX];
__device__ u64 g_a0[NPIX], g_a1p[NPIX], g_b0[NPIX], g_b1p[NPIX], g_sp0[NPIX], g_sp1[NPIX];

// ---------------- grid barrier + per-epoch tile counters ----------------
__device__ unsigned g_count = 0;
__device__ unsigned g_gen   = 0;
__device__ unsigned g_tc[12];

__device__ __forceinline__ unsigned gridbar(unsigned gen, int nb) {
    unsigned next = gen + 1;
    __threadfence();
    __syncthreads();
    if (threadIdx.x == 0) {
        if (atomicAdd(&g_count, 1) == (unsigned)(nb - 1)) {
            g_count = 0;
            __threadfence();
            atomicExch(&g_gen, next);
        } else {
            volatile unsigned* ph = &g_gen;
            while (*ph != next) { __nanosleep(40); }
        }
    }
    __syncthreads();
    __threadfence();
    return next;
}

__device__ __forceinline__ float4 softmax4(float4 z) {
    float m = fmaxf(fmaxf(z.x, z.y), fmaxf(z.z, z.w));
    float ex = __expf(z.x - m), ey = __expf(z.y - m);
    float ez = __expf(z.z - m), ew = __expf(z.w - m);
    float inv = 1.f / (ex + ey + ez + ew);
    return make_float4(ex * inv, ey * inv, ez * inv, ew * inv);
}

// ---- division-free tile loaders: warp w owns rows w, w+8, ... ----
__device__ __forceinline__ void load_tile(u64* dst, const u64* src,
                                          int X0, int Y0, int wid, int lane) {
    for (int r = wid; r < TINY; r += 8) {
        int gy = Y0 + r - RAD;
        bool yok = (unsigned)gy < HEI;
        int gx = X0 + lane - RAD;
        u64 v0 = 0ULL;
        if (yok && (unsigned)gx < WID) v0 = src[gy * WID + gx];
        dst[r * SINP + lane] = v0;
        if (lane < TINX - 32) {
            int gx1 = gx + 32;
            u64 v1 = 0ULL;
            if (yok && (unsigned)gx1 < WID) v1 = src[gy * WID + gx1];
            dst[r * SINP + lane + 32] = v1;
        }
    }
}
__device__ __forceinline__ void load_tile_f(float* dst, const float* src,
                                            int X0, int Y0, int wid, int lane) {
    for (int r = wid; r < TINY; r += 8) {
        int gy = Y0 + r - RAD;
        bool yok = (unsigned)gy < HEI;
        int gx = X0 + lane - RAD;
        float v0 = 0.f;
        if (yok && (unsigned)gx < WID) v0 = src[gy * WID + gx];
        dst[r * SINP + lane] = v0;
        if (lane < TINX - 32) {
            int gx1 = gx + 32;
            float v1 = 0.f;
            if (yok && (unsigned)gx1 < WID) v1 = src[gy * WID + gx1];
            dst[r * SINP + lane + 32] = v1;
        }
    }
}

// H geometry, width-4 chunks (9 tasks over 8 warps; all warps busy)
__device__ __forceinline__ void htask_geom4(int task, int lane, int& row, int& xb) {
    if (task < 8) { row = lane;              xb = task * 4; }
    else          { row = 32 + (lane >> 3);  xb = (lane & 7) * 4; }
}

// ---------------- the persistent kernel ----------------
__global__ void __launch_bounds__(TPB, 4)
k_crf(const float* __restrict__ img, const float4* __restrict__ unary,
      float4* __restrict__ dout, int nb) {
    extern __shared__ char dsm[];
    u64*   sIn  = (u64*)(dsm + OFF_IN0);
    float* sg   = (float*)(dsm + OFF_GRAY);
    u64*   sInB = (u64*)(dsm + OFF_INB);
    u64*   aH0  = (u64*)(dsm + OFF_AH0);
    u64*   aH1  = (u64*)(dsm + OFF_AH1);
    u64*   aH2  = (u64*)(dsm + OFF_AH2);
    u64*   bH0  = (u64*)(dsm + OFF_BH0);
    u64*   bH1  = (u64*)(dsm + OFF_BH1);
    __shared__ int s_t;

    const int tid  = threadIdx.x;
    const int wid  = tid >> 5;
    const int lane = tid & 31;
    const int gid  = blockIdx.x * TPB + tid;
    const int T    = nb * TPB;

    unsigned gen;
    {
        __shared__ unsigned sgen;
        if (tid == 0) sgen = *(volatile unsigned*)&g_gen;
        __syncthreads();
        gen = sgen;
    }

    // ---- P0: grayscale + Q0 = softmax(-unary); zero tile counters ----
    if (gid < 12) g_tc[gid] = 0;
    for (int i = gid; i < NPIX; i += T) {
        float r = img[3 * i], gg = img[3 * i + 1], b = img[3 * i + 2];
        g_gray[i] = 0.2989f * r + 0.5870f * gg + 0.1140f * b;
        float4 u = unary[i];
        float4 q = softmax4(make_float4(-u.x, -u.y, -u.z, -u.w));
        g_Qxy[i] = pk2(q.x, q.y);
        g_Qzw[i] = pk2(q.z, q.w);
    }
    gen = gridbar(gen, nb);

    // ---- PreA (epoch 0): conv2D of (gray, gray^2) -> (mI,iv), (a1,b1) ----
    if (tid == 0) s_t = atomicAdd(&g_tc[0], 1);
    __syncthreads();
    for (int t = s_t; t < NTILES; t = s_t) {
        int X0 = (t & (NTX - 1)) * TSX, Y0 = (t >> 4) * TSY;
        for (int r = wid; r < TINY; r += 8) {           // fill (g, g^2)
            int gy = Y0 + r - RAD;
            bool yok = (unsigned)gy < HEI;
            int gx = X0 + lane - RAD;
            u64 v0 = 0ULL;
            if (yok && (unsigned)gx < WID) { float gv = g_gray[gy * WID + gx]; v0 = pk2(gv, gv * gv); }
            sIn[r * SINP + lane] = v0;
            if (lane < TINX - 32) {
                int gx1 = gx + 32;
                u64 v1 = 0ULL;
                if (yok && (unsigned)gx1 < WID) { float gv = g_gray[gy * WID + gx1]; v1 = pk2(gv, gv * gv); }
                sIn[r * SINP + lane + 32] = v1;
            }
        }
        __syncthreads();
        for (int task = wid; task < 9; task += 8) {
            int row, xb; htask_geom4(task, lane, row, xb);
            u64 a[4] = {0,0,0,0};
            const u64* rw = sIn + row * SINP + xb;
#pragma unroll
            for (int tt = 0; tt < 24; tt++) {
                u64 v = rw[tt];
#pragma unroll
                for (int m = 0; m < 4; m++) {
                    int w = tt - m;
                    if (w >= 0 && w < KS) fma2(a[m], v, wpc(wD(w)));
                }
            }
#pragma unroll
            for (int m = 0; m < 4; m++) aH0[row * SHP + xb + m] = a[m];
        }
        __syncthreads();
        if (wid < 4) {
            int py0 = wid * 4;
            u64 A[4] = {0,0,0,0};
#pragma unroll
            for (int j = 0; j < 24; j++) {
                u64 v = aH0[(py0 + j) * SHP + lane];
#pragma unroll
                for (int m = 0; m < 4; m++) {
                    int w = j - m;
                    if (w >= 0 && w < KS) fma2(A[m], v, wpc(wD(w)));
                }
            }
            float hdx = hsD(X0 + lane);
#pragma unroll
            for (int m = 0; m < 4; m++) {
                int py = py0 + m, gy = Y0 + py, idx = gy * WID + X0 + lane;
                float2 c = up2(A[m]);
                float g = up2(sIn[(py + RAD) * SINP + lane + RAD]).x;
                float mI  = (c.x - g) * SDINV_F;
                float mII = (c.y - g * g) * SDINV_F;
                float mp1 = (hdx * hsD(gy) - 1.f) * SDINV_F;
                float var = mII - mI * mI;
                float iv  = 1.f / (var + 1e-4f);
                float a1  = mI * (1.f - mp1) * iv;
                float b1  = mp1 - a1 * mI;
                g_miv[idx] = pk2(mI, iv);
                g_ab1[idx] = pk2(a1, b1);
            }
        } else if (wid == 7 && lane == 0) {
            s_t = atomicAdd(&g_tc[0], 1);               // grab next tile during V
        }
        __syncthreads();
    }
    gen = gridbar(gen, nb);

    // ---- PreB (epoch 1): conv2D of (a1,b1) -> ibn, spc ----
    if (tid == 0) s_t = atomicAdd(&g_tc[1], 1);
    __syncthreads();
    for (int t = s_t; t < NTILES; t = s_t) {
        int X0 = (t & (NTX - 1)) * TSX, Y0 = (t >> 4) * TSY;
        load_tile(sIn, g_ab1, X0, Y0, wid, lane);
        __syncthreads();
        for (int task = wid; task < 9; task += 8) {
            int row, xb; htask_geom4(task, lane, row, xb);
            u64 a[4] = {0,0,0,0};
            const u64* rw = sIn + row * SINP + xb;
#pragma unroll
            for (int tt = 0; tt < 24; tt++) {
                u64 v = rw[tt];
#pragma unroll
                for (int m = 0; m < 4; m++) {
                    int w = tt - m;
                    if (w >= 0 && w < KS) fma2(a[m], v, wpc(wD(w)));
                }
            }
#pragma unroll
            for (int m = 0; m < 4; m++) aH0[row * SHP + xb + m] = a[m];
        }
        __syncthreads();
        if (wid < 4) {
            int py0 = wid * 4;
            u64 A[4] = {0,0,0,0};
#pragma unroll
            for (int j = 0; j < 24; j++) {
                u64 v = aH0[(py0 + j) * SHP + lane];
#pragma unroll
                for (int m = 0; m < 4; m++) {
                    int w = j - m;
                    if (w >= 0 && w < KS) fma2(A[m], v, wpc(wD(w)));
                }
            }
            float hgx = hsG(X0 + lane);
#pragma unroll
            for (int m = 0; m < 4; m++) {
                int py = py0 + m, gy = Y0 + py, idx = gy * WID + X0 + lane;
                float2 c  = up2(A[m]);
                float2 ab = up2(sIn[(py + RAD) * SINP + lane + RAD]);
                float g = g_gray[idx];
                float gfa = (c.x - ab.x) * SDINV_F;
                float gfb = (c.y - ab.y) * SDINV_F;
                g_ibn[idx] = 10.f / (gfa * g + gfb);
                g_spc[idx] = 3.f / (hgx * hsG(gy) - 1.f);
            }
        } else if (wid == 7 && lane == 0) {
            s_t = atomicAdd(&g_tc[1], 1);
        }
        __syncthreads();
    }
    gen = gridbar(gen, nb);

    // ---- 5 mean-field iterations: 2 tiled phases each ----
    for (int it = 0; it < 5; it++) {
        // ===== PhaseA (epoch 2+2it): conv2D(Q)x{G,D} + conv2D(grayQ)xD -> a,b,sp =====
        {
            const int ep = 2 + 2 * it;
            if (tid == 0) s_t = atomicAdd(&g_tc[ep], 1);
            __syncthreads();
            for (int t = s_t; t < NTILES; t = s_t) {
                int X0 = (t & (NTX - 1)) * TSX, Y0 = (t >> 4) * TSY;
                load_tile_f(sg, g_gray, X0, Y0, wid, lane);
                for (int h = 0; h < 2; h++) {
                    load_tile(sIn, h ? g_Qzw : g_Qxy, X0, Y0, wid, lane);
                    __syncthreads();
                    for (int task = wid; task < 9; task += 8) {
                        int row, xb; htask_geom4(task, lane, row, xb);
                        u64 aD[4] = {0,0,0,0}, aG[4] = {0,0,0,0}, aI[4] = {0,0,0,0};
                        const u64*  rw = sIn + row * SINP + xb;
                        const float* rg = sg + row * SINP + xb;
#pragma unroll
                        for (int tt = 0; tt < 24; tt++) {
                            u64 v = rw[tt];
                            float gf = rg[tt];
                            u64 wv = mul2(v, pk2(gf, gf));
#pragma unroll
                            for (int m = 0; m < 4; m++) {
                                int w = tt - m;
                                if (w >= 0 && w < KS) {
                                    fma2(aD[m], v,  wpc(wD(w)));
                                    fma2(aG[m], v,  wpc(wG(w)));
                                    fma2(aI[m], wv, wpc(wD(w)));
                                }
                            }
                        }
#pragma unroll
                        for (int m = 0; m < 4; m++) {
                            aH0[row * SHP + xb + m] = aD[m];
                            aH1[row * SHP + xb + m] = aG[m];
                            aH2[row * SHP + xb + m] = aI[m];
                        }
                    }
                    __syncthreads();
                    if (wid < 4) {
                        int py0 = wid * 4;
                        u64 AD[4] = {0,0,0,0}, AG[4] = {0,0,0,0}, AI[4] = {0,0,0,0};
#pragma unroll
                        for (int j = 0; j < 24; j++) {
                            u64 v0 = aH0[(py0 + j) * SHP + lane];
                            u64 v1 = aH1[(py0 + j) * SHP + lane];
                            u64 v2 = aH2[(py0 + j) * SHP + lane];
#pragma unroll
                            for (int m = 0; m < 4; m++) {
                                int w = j - m;
                                if (w >= 0 && w < KS) {
                                    fma2(AD[m], v0, wpc(wD(w)));
                                    fma2(AG[m], v1, wpc(wG(w)));
                                    fma2(AI[m], v2, wpc(wD(w)));
                                }
                            }
                        }
#pragma unroll
                        for (int m = 0; m < 4; m++) {
                            int py = py0 + m, idx = (Y0 + py) * WID + X0 + lane;
                            float2 q = up2(sIn[(py + RAD) * SINP + lane + RAD]);
                            float g = sg[(py + RAD) * SINP + lane + RAD];
                            float2 ad = up2(AD[m]), ag = up2(AG[m]), ai = up2(AI[m]);
                            float2 mv = up2(g_miv[idx]);
                            float mI = mv.x, iv = mv.y, spc = g_spc[idx];
                            float spx = (ag.x - q.x) * spc,         spy = (ag.y - q.y) * spc;
                            float mpx = (ad.x - q.x) * SDINV_F,     mpy = (ad.y - q.y) * SDINV_F;
                            float mix = (ai.x - g * q.x) * SDINV_F, miy = (ai.y - g * q.y) * SDINV_F;
                            float ax = (mix - mI * mpx) * iv,       ay = (miy - mI * mpy) * iv;
                            float bx = mpx - ax * mI,               by = mpy - ay * mI;
                            if (h == 0) {
                                g_a0[idx]  = pk2(ax, ay);
                                g_b0[idx]  = pk2(bx, by);
                                g_sp0[idx] = pk2(spx, spy);
                            } else {
                                g_a1p[idx] = pk2(ax, ay);
                                g_b1p[idx] = pk2(bx, by);
                                g_sp1[idx] = pk2(spx, spy);
                            }
                        }
                    } else if (h == 1 && wid == 7 && lane == 0) {
                        s_t = atomicAdd(&g_tc[ep], 1);
                    }
                    __syncthreads();
                }
            }
            gen = gridbar(gen, nb);
        }

        // ===== PhaseB (epoch 3+2it): conv2D(a,b) + message + softmax -> Q / dout =====
        {
            const int ep = 3 + 2 * it;
            if (tid == 0) s_t = atomicAdd(&g_tc[ep], 1);
            __syncthreads();
            for (int t = s_t; t < NTILES; t = s_t) {
                int X0 = (t & (NTX - 1)) * TSX, Y0 = (t >> 4) * TSY;
                float z0[8];
                for (int h = 0; h < 2; h++) {
                    load_tile(sIn,  h ? g_a1p : g_a0, X0, Y0, wid, lane);
                    load_tile(sInB, h ? g_b1p : g_b0, X0, Y0, wid, lane);
                    __syncthreads();
                    for (int task = wid; task < 9; task += 8) {
                        int row, xb; htask_geom4(task, lane, row, xb);
                        u64 aA[4] = {0,0,0,0}, aB[4] = {0,0,0,0};
                        const u64* rwA = sIn  + row * SINP + xb;
                        const u64* rwB = sInB + row * SINP + xb;
#pragma unroll
                        for (int tt = 0; tt < 24; tt++) {
                            u64 vA = rwA[tt], vB = rwB[tt];
#pragma unroll
                            for (int m = 0; m < 4; m++) {
                                int w = tt - m;
                                if (w >= 0 && w < KS) {
                                    fma2(aA[m], vA, wpc(wD(w)));
                                    fma2(aB[m], vB, wpc(wD(w)));
                                }
                            }
                        }
#pragma unroll
                        for (int m = 0; m < 4; m++) {
                            bH0[row * SHP + xb + m] = aA[m];
                            bH1[row * SHP + xb + m] = aB[m];
                        }
                    }
                    __syncthreads();
                    if (wid < 4) {
                        int py0 = wid * 4;
                        u64 AA[4] = {0,0,0,0}, AB[4] = {0,0,0,0};
#pragma unroll
                        for (int j = 0; j < 24; j++) {
                            u64 v0 = bH0[(py0 + j) * SHP + lane];
                            u64 v1 = bH1[(py0 + j) * SHP + lane];
#pragma unroll
                            for (int m = 0; m < 4; m++) {
                                int w = j - m;
                                if (w >= 0 && w < KS) {
                                    fma2(AA[m], v0, wpc(wD(w)));
                                    fma2(AB[m], v1, wpc(wD(w)));
                                }
                            }
                        }
#pragma unroll
                        for (int m = 0; m < 4; m++) {
                            int py = py0 + m, idx = (Y0 + py) * WID + X0 + lane;
                            float2 ac = up2(sIn [(py + RAD) * SINP + lane + RAD]);
                            float2 bc = up2(sInB[(py + RAD) * SINP + lane + RAD]);
                            float2 aa = up2(AA[m]), ab = up2(AB[m]);
                            float2 sp = up2(h ? g_sp1[idx] : g_sp0[idx]);
                            float ibn = g_ibn[idx], g = g_gray[idx];
                            float2 uu = *((const float2*)unary + 2 * idx + h);
                            float zx = sp.x + ((aa.x - ac.x) * SDINV_F * g
                                             + (ab.x - bc.x) * SDINV_F) * ibn - uu.x;
                            float zy = sp.y + ((aa.y - ac.y) * SDINV_F * g
                                             + (ab.y - bc.y) * SDINV_F) * ibn - uu.y;
                            if (h == 0) {
                                z0[2*m] = zx; z0[2*m+1] = zy;
                            } else {
                                float4 q = softmax4(make_float4(z0[2*m], z0[2*m+1], zx, zy));
                                if (it == 4) {
                                    dout[idx] = q;
                                } else {
                                    g_Qxy[idx] = pk2(q.x, q.y);
                                    g_Qzw[idx] = pk2(q.z, q.w);
                                }
                            }
                        }
                    } else if (h == 1 && wid == 7 && lane == 0) {
                        s_t = atomicAdd(&g_tc[ep], 1);
                    }
                    __syncthreads();
                }
            }
            if (it < 4) gen = gridbar(gen, nb);
        }
    }
}

// ---------------- launch ----------------
extern "C" void kernel_launch(void* const* d_in, const int* in_sizes, int n_in,
                              void* d_out, int out_size) {
    const float* unary = nullptr;
    const float* image = nullptr;
    for (int i = 0; i < n_in; i++) {
        if (in_sizes[i] == NPIX * 4) unary = (const float*)d_in[i];
        else if (in_sizes[i] == NPIX * 3) image = (const float*)d_in[i];
    }

    cudaFuncSetAttribute(k_crf, cudaFuncAttributeMaxDynamicSharedMemorySize, SMEM_BYTES);

    int sms = 0, occ = 0;
    cudaDeviceGetAttribute(&sms, cudaDevAttrMultiProcessorCount, 0);
    cudaOccupancyMaxActiveBlocksPerMultiprocessor(&occ, k_crf, TPB, SMEM_BYTES);
    if (sms <= 0) sms = 148;
    if (occ <= 0) occ = 1;
    int nb = sms * occ;
    if (nb > 1024) nb = 1024;

    k_crf<<<nb, TPB, SMEM_BYTES>>>(image, (const float4*)unary, (float4*)d_out, nb);
}

// round 13
// speedup vs baseline: 1.0273x; 1.0066x over previous
#include <cuda_runtime.h>

#define WID 512
#define HEI 512
#define NPIX (WID*HEI)
#define RAD 10
#define KS 21
#define TPB 256
#define TSX 32
#define TSY 32
#define TINX 52
#define TINY 52
#define SINP 53                 // padded input tile stride (u64 units; odd -> CF column access)
#define SHP  33                 // padded H-buffer stride (odd -> CF column access)
#define NTX (WID/TSX)           // 16
#define NTY (HEI/TSY)           // 16
#define NTILES (NTX*NTY)        // 256
#define NELEM (TINY*SINP)       // 2756

// smem layout (bytes) — overlap-packed per phase
#define OFF_IN0   0                       // u64[52*53] = 22048
#define OFF_GRAY  22048                   // float[52*53] = 11024 (PhaseA)
#define OFF_INB   22048                   // u64 tile = 22048 (PhaseB second input)
#define OFF_AH0   33072                   // H buffers: u64[52*33] = 13728
#define OFF_AH1   46800
#define OFF_AH2   60528
#define OFF_BH0   44096
#define OFF_BH1   57824
#define SMEM_BYTES 74256

typedef unsigned long long u64;

// ---------------- compile-time weights ----------------
constexpr double cexp(double x) {
    double y = x / 16.0, s = 1.0, t = 1.0;
    for (int i = 1; i < 40; i++) { t *= y / (double)i; s += t; }
    s = s * s; s = s * s; s = s * s; s = s * s;
    return s;
}
constexpr double wgd(int t) { double d = (double)(t - RAD); return cexp(-d * d / 12.5); }
constexpr double wdd(int t) { double d = (double)(t - RAD); return cexp(-d * d * 9.0 / 200.0); }
constexpr double sumw(int wh) { double s = 0; for (int i = 0; i < KS; i++) s += (wh ? wgd(i) : wdd(i)); return s; }
constexpr double pref(int wh, int n) { double s = 0; for (int i = 0; i < n; i++) s += (wh ? wgd(i) : wdd(i)); return s; }

constexpr float SD_F    = (float)sumw(0);
constexpr float SG_F    = (float)sumw(1);
constexpr float SDINV_F = (float)(1.0 / (sumw(0) * sumw(0)));

#define TAPLIST(F) F(0) F(1) F(2) F(3) F(4) F(5) F(6) F(7) F(8) F(9) F(10) \
                   F(11) F(12) F(13) F(14) F(15) F(16) F(17) F(18) F(19) F(20)
#define DWG(i) constexpr float WG_##i = (float)wgd(i);
#define DWD(i) constexpr float WD_##i = (float)wdd(i);
TAPLIST(DWG)
TAPLIST(DWD)

__device__ __forceinline__ float wG(int t) {
    switch (t) {
#define CWG(i) case i: return WG_##i;
        TAPLIST(CWG)
#undef CWG
    }
    return 0.f;
}
__device__ __forceinline__ float wD(int t) {
    switch (t) {
#define CWD(i) case i: return WD_##i;
        TAPLIST(CWD)
#undef CWD
    }
    return 0.f;
}

__constant__ float c_pD[11] = {
    (float)pref(0,0),(float)pref(0,1),(float)pref(0,2),(float)pref(0,3),(float)pref(0,4),
    (float)pref(0,5),(float)pref(0,6),(float)pref(0,7),(float)pref(0,8),(float)pref(0,9),
    (float)pref(0,10)
};
__constant__ float c_pG[11] = {
    (float)pref(1,0),(float)pref(1,1),(float)pref(1,2),(float)pref(1,3),(float)pref(1,4),
    (float)pref(1,5),(float)pref(1,6),(float)pref(1,7),(float)pref(1,8),(float)pref(1,9),
    (float)pref(1,10)
};

__device__ __forceinline__ float hsD(int x) {
    float s = SD_F;
    if (x < RAD) s -= c_pD[RAD - x];
    if (x > WID - 1 - RAD) s -= c_pD[x - (WID - 1 - RAD)];
    return s;
}
__device__ __forceinline__ float hsG(int x) {
    float s = SG_F;
    if (x < RAD) s -= c_pG[RAD - x];
    if (x > WID - 1 - RAD) s -= c_pG[x - (WID - 1 - RAD)];
    return s;
}

// ---------------- packed f32x2 helpers ----------------
__device__ __forceinline__ u64 pk2(float x, float y) {
    u64 r; asm("mov.b64 %0,{%1,%2};" : "=l"(r) : "f"(x), "f"(y)); return r;
}
__device__ __forceinline__ float2 up2(u64 v) {
    float2 o; asm("mov.b64 {%0,%1},%2;" : "=f"(o.x), "=f"(o.y) : "l"(v)); return o;
}
__device__ __forceinline__ void fma2(u64& d, u64 a, u64 b) {
    asm("fma.rn.f32x2 %0,%1,%2,%0;" : "+l"(d) : "l"(a), "l"(b));
}
__device__ __forceinline__ u64 mul2(u64 a, u64 b) {
    u64 r; asm("mul.rn.f32x2 %0,%1,%2;" : "=l"(r) : "l"(a), "l"(b)); return r;
}
__device__ __forceinline__ u64 wpc(float w) {   // (w,w) pair; constant-folds after unroll
    unsigned u = __float_as_uint(w);
    return ((u64)u << 32) | (u64)u;
}

// ---------------- static device planes ----------------
__device__ float g_gray[NPIX], g_mI[NPIX], g_iv[NPIX], g_ibn[NPIX], g_spc[NPIX];
__device__ u64 g_ab1[NPIX];
__device__ u64 g_Qxy[NPIX], g_Qzw[NPIX];
__device__ u64 g_a0[NPIX], g_a1p[NPIX], g_b0[NPIX], g_b1p[NPIX], g_sp0[NPIX], g_sp1[NPIX];

// ---------------- grid barrier ----------------
__device__ unsigned g_count = 0;
__device__ unsigned g_gen   = 0;

__device__ __forceinline__ unsigned gridbar(unsigned gen, int nb) {
    unsigned next = gen + 1;
    __threadfence();
    __syncthreads();
    if (threadIdx.x == 0) {
        if (atomicAdd(&g_count, 1) == (unsigned)(nb - 1)) {
            g_count = 0;
            __threadfence();
            atomicExch(&g_gen, next);
        } else {
            volatile unsigned* ph = &g_gen;
            while (*ph != next) { __nanosleep(40); }
        }
    }
    __syncthreads();
    __threadfence();
    return next;
}

__device__ __forceinline__ float4 softmax4(float4 z) {
    float m = fmaxf(fmaxf(z.x, z.y), fmaxf(z.z, z.w));
    float ex = __expf(z.x - m), ey = __expf(z.y - m);
    float ez = __expf(z.z - m), ew = __expf(z.w - m);
    float inv = 1.f / (ex + ey + ez + ew);
    return make_float4(ex * inv, ey * inv, ez * inv, ew * inv);
}

// R10-style division-based tile loader (zero-padded halo)
__device__ __forceinline__ void load_tile(u64* dst, const u64* src,
                                          int X0, int Y0, int tid) {
    for (int s = tid; s < NELEM; s += TPB) {
        int r = s / SINP, c = s - r * SINP;
        int gx = X0 + c - RAD, gy = Y0 + r - RAD;
        u64 v = 0ULL;
        if (c < TINX && (unsigned)gx < WID && (unsigned)gy < HEI) v = src[gy * WID + gx];
        dst[s] = v;
    }
}

// H geometry: 13 warp-tasks cover 52 rows x 8 x-chunks (width 4)
__device__ __forceinline__ void htask_geom(int task, int lane, int& row, int& xb) {
    if (task < 8) { row = lane;                              xb = task * 4; }
    else          { row = 32 + (task - 8) * 4 + (lane >> 3); xb = (lane & 7) * 4; }
}

// ---------------- the persistent kernel ----------------
__global__ void __launch_bounds__(TPB, 3)
k_crf(const float* __restrict__ img, const float4* __restrict__ unary,
      float4* __restrict__ dout, int nb) {
    extern __shared__ char dsm[];
    u64*   sIn  = (u64*)(dsm + OFF_IN0);
    float* sg   = (float*)(dsm + OFF_GRAY);
    u64*   sInB = (u64*)(dsm + OFF_INB);
    u64*   aH0  = (u64*)(dsm + OFF_AH0);
    u64*   aH1  = (u64*)(dsm + OFF_AH1);
    u64*   aH2  = (u64*)(dsm + OFF_AH2);
    u64*   bH0  = (u64*)(dsm + OFF_BH0);
    u64*   bH1  = (u64*)(dsm + OFF_BH1);

    const int tid  = threadIdx.x;
    const int wid  = tid >> 5;
    const int lane = tid & 31;
    const int gid  = blockIdx.x * TPB + tid;
    const int T    = nb * TPB;

    unsigned gen;
    {
        __shared__ unsigned sgen;
        if (tid == 0) sgen = *(volatile unsigned*)&g_gen;
        __syncthreads();
        gen = sgen;
    }

    // ---- P0: grayscale + Q0 = softmax(-unary) ----
    for (int i = gid; i < NPIX; i += T) {
        float r = img[3 * i], gg = img[3 * i + 1], b = img[3 * i + 2];
        g_gray[i] = 0.2989f * r + 0.5870f * gg + 0.1140f * b;
        float4 u = unary[i];
        float4 q = softmax4(make_float4(-u.x, -u.y, -u.z, -u.w));
        g_Qxy[i] = pk2(q.x, q.y);
        g_Qzw[i] = pk2(q.z, q.w);
    }
    gen = gridbar(gen, nb);

    // ---- PreA: conv2D of (gray, gray^2) -> mI, iv, (a1,b1) ----
    for (int t = blockIdx.x; t < NTILES; t += nb) {
        int X0 = (t & (NTX - 1)) * TSX, Y0 = (t >> 4) * TSY;
        for (int s = tid; s < NELEM; s += TPB) {
            int r = s / SINP, c = s - r * SINP;
            int gx = X0 + c - RAD, gy = Y0 + r - RAD;
            u64 v = 0ULL;
            if (c < TINX && (unsigned)gx < WID && (unsigned)gy < HEI) {
                float gv = g_gray[gy * WID + gx];
                v = pk2(gv, gv * gv);
            }
            sIn[s] = v;
        }
        __syncthreads();
        for (int task = wid; task < 13; task += 8) {
            int row, xb; htask_geom(task, lane, row, xb);
            u64 a[4] = {0,0,0,0};
            const u64* rw = sIn + row * SINP + xb;
#pragma unroll
            for (int tt = 0; tt < 24; tt++) {
                u64 v = rw[tt];
#pragma unroll
                for (int m = 0; m < 4; m++) {
                    int w = tt - m;
                    if (w >= 0 && w < KS) fma2(a[m], v, wpc(wD(w)));
                }
            }
#pragma unroll
            for (int m = 0; m < 4; m++) aH0[row * SHP + xb + m] = a[m];
        }
        __syncthreads();
        {
            int py0 = wid * 4;
            u64 A[4] = {0,0,0,0};
#pragma unroll
            for (int j = 0; j < 24; j++) {
                u64 v = aH0[(py0 + j) * SHP + lane];
#pragma unroll
                for (int m = 0; m < 4; m++) {
                    int w = j - m;
                    if (w >= 0 && w < KS) fma2(A[m], v, wpc(wD(w)));
                }
            }
            float hdx = hsD(X0 + lane);
#pragma unroll
            for (int m = 0; m < 4; m++) {
                int py = py0 + m, gy = Y0 + py, idx = gy * WID + X0 + lane;
                float2 c = up2(A[m]);
                float g = up2(sIn[(py + RAD) * SINP + lane + RAD]).x;
                float mI  = (c.x - g) * SDINV_F;
                float mII = (c.y - g * g) * SDINV_F;
                float mp1 = (hdx * hsD(gy) - 1.f) * SDINV_F;
                float var = mII - mI * mI;
                float iv  = 1.f / (var + 1e-4f);
                float a1  = mI * (1.f - mp1) * iv;
                float b1  = mp1 - a1 * mI;
                g_mI[idx] = mI; g_iv[idx] = iv; g_ab1[idx] = pk2(a1, b1);
            }
        }
        __syncthreads();
    }
    gen = gridbar(gen, nb);

    // ---- PreB: conv2D of (a1,b1) -> ibn, spc ----
    for (int t = blockIdx.x; t < NTILES; t += nb) {
        int X0 = (t & (NTX - 1)) * TSX, Y0 = (t >> 4) * TSY;
        load_tile(sIn, g_ab1, X0, Y0, tid);
        __syncthreads();
        for (int task = wid; task < 13; task += 8) {
            int row, xb; htask_geom(task, lane, row, xb);
            u64 a[4] = {0,0,0,0};
            const u64* rw = sIn + row * SINP + xb;
#pragma unroll
            for (int tt = 0; tt < 24; tt++) {
                u64 v = rw[tt];
#pragma unroll
                for (int m = 0; m < 4; m++) {
                    int w = tt - m;
                    if (w >= 0 && w < KS) fma2(a[m], v, wpc(wD(w)));
                }
            }
#pragma unroll
            for (int m = 0; m < 4; m++) aH0[row * SHP + xb + m] = a[m];
        }
        __syncthreads();
        {
            int py0 = wid * 4;
            u64 A[4] = {0,0,0,0};
#pragma unroll
            for (int j = 0; j < 24; j++) {
                u64 v = aH0[(py0 + j) * SHP + lane];
#pragma unroll
                for (int m = 0; m < 4; m++) {
                    int w = j - m;
                    if (w >= 0 && w < KS) fma2(A[m], v, wpc(wD(w)));
                }
            }
            float hgx = hsG(X0 + lane);
#pragma unroll
            for (int m = 0; m < 4; m++) {
                int py = py0 + m, gy = Y0 + py, idx = gy * WID + X0 + lane;
                float2 c  = up2(A[m]);
                float2 ab = up2(sIn[(py + RAD) * SINP + lane + RAD]);
                float g = g_gray[idx];
                float gfa = (c.x - ab.x) * SDINV_F;
                float gfb = (c.y - ab.y) * SDINV_F;
                g_ibn[idx] = 10.f / (gfa * g + gfb);
                g_spc[idx] = 3.f / (hgx * hsG(gy) - 1.f);
            }
        }
        __syncthreads();
    }
    gen = gridbar(gen, nb);

    // ---- 5 mean-field iterations: 2 tiled phases each ----
    for (int it = 0; it < 5; it++) {
        // ===== PhaseA: conv2D(Q)x{G,D} + conv2D(grayQ)xD -> a,b,sp =====
        for (int t = blockIdx.x; t < NTILES; t += nb) {
            int X0 = (t & (NTX - 1)) * TSX, Y0 = (t >> 4) * TSY;
            for (int s = tid; s < NELEM; s += TPB) {
                int r = s / SINP, c = s - r * SINP;
                int gx = X0 + c - RAD, gy = Y0 + r - RAD;
                float v = 0.f;
                if (c < TINX && (unsigned)gx < WID && (unsigned)gy < HEI) v = g_gray[gy * WID + gx];
                sg[s] = v;
            }
            for (int h = 0; h < 2; h++) {
                load_tile(sIn, h ? g_Qzw : g_Qxy, X0, Y0, tid);
                __syncthreads();
                for (int task = wid; task < 13; task += 8) {
                    int row, xb; htask_geom(task, lane, row, xb);
                    u64 aD[4] = {0,0,0,0}, aG[4] = {0,0,0,0}, aI[4] = {0,0,0,0};
                    const u64*  rw = sIn + row * SINP + xb;
                    const float* rg = sg + row * SINP + xb;
#pragma unroll
                    for (int tt = 0; tt < 24; tt++) {
                        u64 v = rw[tt];
                        float gf = rg[tt];
                        u64 wv = mul2(v, pk2(gf, gf));
#pragma unroll
                        for (int m = 0; m < 4; m++) {
                            int w = tt - m;
                            if (w >= 0 && w < KS) {
                                fma2(aD[m], v,  wpc(wD(w)));
                                fma2(aG[m], v,  wpc(wG(w)));
                                fma2(aI[m], wv, wpc(wD(w)));
                            }
                        }
                    }
#pragma unroll
                    for (int m = 0; m < 4; m++) {
                        aH0[row * SHP + xb + m] = aD[m];
                        aH1[row * SHP + xb + m] = aG[m];
                        aH2[row * SHP + xb + m] = aI[m];
                    }
                }
                __syncthreads();
                {
                    int py0 = wid * 4;
                    u64 AD[4] = {0,0,0,0}, AG[4] = {0,0,0,0}, AI[4] = {0,0,0,0};
#pragma unroll
                    for (int j = 0; j < 24; j++) {
                        u64 v0 = aH0[(py0 + j) * SHP + lane];
                        u64 v1 = aH1[(py0 + j) * SHP + lane];
                        u64 v2 = aH2[(py0 + j) * SHP + lane];
#pragma unroll
                        for (int m = 0; m < 4; m++) {
                            int w = j - m;
                            if (w >= 0 && w < KS) {
                                fma2(AD[m], v0, wpc(wD(w)));
                                fma2(AG[m], v1, wpc(wG(w)));
                                fma2(AI[m], v2, wpc(wD(w)));
                            }
                        }
                    }
#pragma unroll
                    for (int m = 0; m < 4; m++) {
                        int py = py0 + m, idx = (Y0 + py) * WID + X0 + lane;
                        float2 q = up2(sIn[(py + RAD) * SINP + lane + RAD]);
                        float g = sg[(py + RAD) * SINP + lane + RAD];
                        float2 ad = up2(AD[m]), ag = up2(AG[m]), ai = up2(AI[m]);
                        float mI = g_mI[idx], iv = g_iv[idx], spc = g_spc[idx];
                        float spx = (ag.x - q.x) * spc,         spy = (ag.y - q.y) * spc;
                        float mpx = (ad.x - q.x) * SDINV_F,     mpy = (ad.y - q.y) * SDINV_F;
                        float mix = (ai.x - g * q.x) * SDINV_F, miy = (ai.y - g * q.y) * SDINV_F;
                        float ax = (mix - mI * mpx) * iv,       ay = (miy - mI * mpy) * iv;
                        float bx = mpx - ax * mI,               by = mpy - ay * mI;
                        if (h == 0) {
                            g_a0[idx]  = pk2(ax, ay);
                            g_b0[idx]  = pk2(bx, by);
                            g_sp0[idx] = pk2(spx, spy);
                        } else {
                            g_a1p[idx] = pk2(ax, ay);
                            g_b1p[idx] = pk2(bx, by);
                            g_sp1[idx] = pk2(spx, spy);
                        }
                    }
                }
                __syncthreads();
            }
        }
        gen = gridbar(gen, nb);

        // ===== PhaseB: conv2D(a,b) + message + softmax -> Q / dout =====
        for (int t = blockIdx.x; t < NTILES; t += nb) {
            int X0 = (t & (NTX - 1)) * TSX, Y0 = (t >> 4) * TSY;
            float z0[8];
            for (int h = 0; h < 2; h++) {
                load_tile(sIn,  h ? g_a1p : g_a0, X0, Y0, tid);
                load_tile(sInB, h ? g_b1p : g_b0, X0, Y0, tid);
                __syncthreads();
                for (int task = wid; task < 13; task += 8) {
                    int row, xb; htask_geom(task, lane, row, xb);
                    u64 aA[4] = {0,0,0,0}, aB[4] = {0,0,0,0};
                    const u64* rwA = sIn  + row * SINP + xb;
                    const u64* rwB = sInB + row * SINP + xb;
#pragma unroll
                    for (int tt = 0; tt < 24; tt++) {
                        u64 vA = rwA[tt], vB = rwB[tt];
#pragma unroll
                        for (int m = 0; m < 4; m++) {
                            int w = tt - m;
                            if (w >= 0 && w < KS) {
                                fma2(aA[m], vA, wpc(wD(w)));
                                fma2(aB[m], vB, wpc(wD(w)));
                            }
                        }
                    }
#pragma unroll
                    for (int m = 0; m < 4; m++) {
                        bH0[row * SHP + xb + m] = aA[m];
                        bH1[row * SHP + xb + m] = aB[m];
                    }
                }
                __syncthreads();
                {
                    int py0 = wid * 4;
                    u64 AA[4] = {0,0,0,0}, AB[4] = {0,0,0,0};
#pragma unroll
                    for (int j = 0; j < 24; j++) {
                        u64 v0 = bH0[(py0 + j) * SHP + lane];
                        u64 v1 = bH1[(py0 + j) * SHP + lane];
#pragma unroll
                        for (int m = 0; m < 4; m++) {
                            int w = j - m;
                            if (w >= 0 && w < KS) {
                                fma2(AA[m], v0, wpc(wD(w)));
                                fma2(AB[m], v1, wpc(wD(w)));
                            }
                        }
                    }
#pragma unroll
                    for (int m = 0; m < 4; m++) {
                        int py = py0 + m, idx = (Y0 + py) * WID + X0 + lane;
                        float2 ac = up2(sIn [(py + RAD) * SINP + lane + RAD]);
                        float2 bc = up2(sInB[(py + RAD) * SINP + lane + RAD]);
                        float2 aa = up2(AA[m]), ab = up2(AB[m]);
                        float2 sp = up2(h ? g_sp1[idx] : g_sp0[idx]);
                        float ibn = g_ibn[idx], g = g_gray[idx];
                        float2 uu = *((const float2*)unary + 2 * idx + h);
                        float zx = sp.x + ((aa.x - ac.x) * SDINV_F * g
                                         + (ab.x - bc.x) * SDINV_F) * ibn - uu.x;
                        float zy = sp.y + ((aa.y - ac.y) * SDINV_F * g
                                         + (ab.y - bc.y) * SDINV_F) * ibn - uu.y;
                        if (h == 0) {
                            z0[2*m] = zx; z0[2*m+1] = zy;
                        } else {
                            float4 q = softmax4(make_float4(z0[2*m], z0[2*m+1], zx, zy));
                            if (it == 4) {
                                dout[idx] = q;
                            } else {
                                g_Qxy[idx] = pk2(q.x, q.y);
                                g_Qzw[idx] = pk2(q.z, q.w);
                            }
                        }
                    }
                }
                __syncthreads();
            }
        }
        if (it < 4) gen = gridbar(gen, nb);
    }
}

// ---------------- launch ----------------
extern "C" void kernel_launch(void* const* d_in, const int* in_sizes, int n_in,
                              void* d_out, int out_size) {
    const float* unary = nullptr;
    const float* image = nullptr;
    for (int i = 0; i < n_in; i++) {
        if (in_sizes[i] == NPIX * 4) unary = (const float*)d_in[i];
        else if (in_sizes[i] == NPIX * 3) image = (const float*)d_in[i];
    }

    cudaFuncSetAttribute(k_crf, cudaFuncAttributeMaxDynamicSharedMemorySize, SMEM_BYTES);

    int sms = 0, occ = 0;
    cudaDeviceGetAttribute(&sms, cudaDevAttrMultiProcessorCount, 0);
    cudaOccupancyMaxActiveBlocksPerMultiprocessor(&occ, k_crf, TPB, SMEM_BYTES);
    if (sms <= 0) sms = 148;
    if (occ <= 0) occ = 1;
    int nb = sms * occ;
    if (nb > 1024) nb = 1024;

    k_crf<<<nb, TPB, SMEM_BYTES>>>(image, (const float4*)unary, (float4*)d_out, nb);
}

// round 14
// speedup vs baseline: 1.1411x; 1.1107x over previous
#include <cuda_runtime.h>

#define WID 512
#define HEI 512
#define NPIX (WID*HEI)
#define RAD 10
#define KS 21
#define TPB 256
#define TSX 32
#define TSY 16
#define TINX 52
#define TINY 36
#define SINP 53                 // padded input tile stride (u64 units; odd -> CF column access)
#define SHP  33                 // padded H-buffer stride (odd -> CF column access)
#define SVP  33                 // V staging stride
#define NTX (WID/TSX)           // 16
#define NTY (HEI/TSY)           // 32
#define NTILES (NTX*NTY)        // 512
#define NELEM (TINY*SINP)       // 1908

// smem layout (bytes) — overlap-packed per phase
#define OFF_IN0   0                       // u64[36*53] = 15264
#define OFF_GRAY  15264                   // float[36*53] = 7632  (PhaseA)
#define OFF_INB   15264                   // u64 tile (PhaseB second input)
#define OFF_AH0   22896                   // H buffers: u64[36*33] = 9504
#define OFF_AH1   32400
#define OFF_AH2   41904
#define OFF_BH0   30528
#define OFF_BH1   40032
#define OFF_SV    51408                   // V staging: u64[16*33] = 4224
#define SMEM_BYTES 55632

typedef unsigned long long u64;

// ---------------- compile-time weights ----------------
constexpr double cexp(double x) {
    double y = x / 16.0, s = 1.0, t = 1.0;
    for (int i = 1; i < 40; i++) { t *= y / (double)i; s += t; }
    s = s * s; s = s * s; s = s * s; s = s * s;
    return s;
}
constexpr double wgd(int t) { double d = (double)(t - RAD); return cexp(-d * d / 12.5); }
constexpr double wdd(int t) { double d = (double)(t - RAD); return cexp(-d * d * 9.0 / 200.0); }
constexpr double sumw(int wh) { double s = 0; for (int i = 0; i < KS; i++) s += (wh ? wgd(i) : wdd(i)); return s; }
constexpr double pref(int wh, int n) { double s = 0; for (int i = 0; i < n; i++) s += (wh ? wgd(i) : wdd(i)); return s; }

constexpr float SD_F    = (float)sumw(0);
constexpr float SG_F    = (float)sumw(1);
constexpr float SDINV_F = (float)(1.0 / (sumw(0) * sumw(0)));

#define TAPLIST(F) F(0) F(1) F(2) F(3) F(4) F(5) F(6) F(7) F(8) F(9) F(10) \
                   F(11) F(12) F(13) F(14) F(15) F(16) F(17) F(18) F(19) F(20)
#define DWG(i) constexpr float WG_##i = (float)wgd(i);
#define DWD(i) constexpr float WD_##i = (float)wdd(i);
TAPLIST(DWG)
TAPLIST(DWD)

__device__ __forceinline__ float wG(int t) {
    switch (t) {
#define CWG(i) case i: return WG_##i;
        TAPLIST(CWG)
#undef CWG
    }
    return 0.f;
}
__device__ __forceinline__ float wD(int t) {
    switch (t) {
#define CWD(i) case i: return WD_##i;
        TAPLIST(CWD)
#undef CWD
    }
    return 0.f;
}

__constant__ float c_pD[11] = {
    (float)pref(0,0),(float)pref(0,1),(float)pref(0,2),(float)pref(0,3),(float)pref(0,4),
    (float)pref(0,5),(float)pref(0,6),(float)pref(0,7),(float)pref(0,8),(float)pref(0,9),
    (float)pref(0,10)
};
__constant__ float c_pG[11] = {
    (float)pref(1,0),(float)pref(1,1),(float)pref(1,2),(float)pref(1,3),(float)pref(1,4),
    (float)pref(1,5),(float)pref(1,6),(float)pref(1,7),(float)pref(1,8),(float)pref(1,9),
    (float)pref(1,10)
};

__device__ __forceinline__ float hsD(int x) {
    float s = SD_F;
    if (x < RAD) s -= c_pD[RAD - x];
    if (x > WID - 1 - RAD) s -= c_pD[x - (WID - 1 - RAD)];
    return s;
}
__device__ __forceinline__ float hsG(int x) {
    float s = SG_F;
    if (x < RAD) s -= c_pG[RAD - x];
    if (x > WID - 1 - RAD) s -= c_pG[x - (WID - 1 - RAD)];
    return s;
}

// ---------------- packed f32x2 helpers ----------------
__device__ __forceinline__ u64 pk2(float x, float y) {
    u64 r; asm("mov.b64 %0,{%1,%2};" : "=l"(r) : "f"(x), "f"(y)); return r;
}
__device__ __forceinline__ float2 up2(u64 v) {
    float2 o; asm("mov.b64 {%0,%1},%2;" : "=f"(o.x), "=f"(o.y) : "l"(v)); return o;
}
__device__ __forceinline__ void fma2(u64& d, u64 a, u64 b) {
    asm("fma.rn.f32x2 %0,%1,%2,%0;" : "+l"(d) : "l"(a), "l"(b));
}
__device__ __forceinline__ u64 mul2(u64 a, u64 b) {
    u64 r; asm("mul.rn.f32x2 %0,%1,%2;" : "=l"(r) : "l"(a), "l"(b)); return r;
}
__device__ __forceinline__ u64 wpc(float w) {   // (w,w) pair; constant-folds after unroll
    unsigned u = __float_as_uint(w);
    return ((u64)u << 32) | (u64)u;
}

// ---------------- static device planes ----------------
__device__ float g_gray[NPIX], g_mI[NPIX], g_iv[NPIX], g_ibn[NPIX], g_spc[NPIX];
__device__ u64 g_ab1[NPIX];
__device__ u64 g_Qxy[NPIX], g_Qzw[NPIX];
__device__ u64 g_a0[NPIX], g_a1p[NPIX], g_b0[NPIX], g_b1p[NPIX], g_sp0[NPIX], g_sp1[NPIX];

// ---------------- grid barrier ----------------
__device__ unsigned g_count = 0;
__device__ unsigned g_gen   = 0;

__device__ __forceinline__ unsigned gridbar(unsigned gen, int nb) {
    unsigned next = gen + 1;
    __threadfence();
    __syncthreads();
    if (threadIdx.x == 0) {
        if (atomicAdd(&g_count, 1) == (unsigned)(nb - 1)) {
            g_count = 0;
            __threadfence();
            atomicExch(&g_gen, next);
        } else {
            volatile unsigned* ph = &g_gen;
            while (*ph != next) { __nanosleep(40); }
        }
    }
    __syncthreads();
    __threadfence();
    return next;
}

__device__ __forceinline__ float4 softmax4(float4 z) {
    float m = fmaxf(fmaxf(z.x, z.y), fmaxf(z.z, z.w));
    float ex = __expf(z.x - m), ey = __expf(z.y - m);
    float ez = __expf(z.z - m), ew = __expf(z.w - m);
    float inv = 1.f / (ex + ey + ez + ew);
    return make_float4(ex * inv, ey * inv, ez * inv, ew * inv);
}

// R10-style division-based tile loader (zero-padded halo)
__device__ __forceinline__ void load_tile(u64* dst, const u64* src,
                                          int X0, int Y0, int tid) {
    for (int s = tid; s < NELEM; s += TPB) {
        int r = s / SINP, c = s - r * SINP;
        int gx = X0 + c - RAD, gy = Y0 + r - RAD;
        u64 v = 0ULL;
        if (c < TINX && (unsigned)gx < WID && (unsigned)gy < HEI) v = src[gy * WID + gx];
        dst[s] = v;
    }
}

// H task geometry: tasks 0..7 = column chunk (xb=task*4), rows = lane (0..31).
// task 8 = tail rows 32..35: lane = (row-32)*8 + chunk.
__device__ __forceinline__ void htask_geom(int task, int lane, int& row, int& xb) {
    if (task < 8) { row = lane;              xb = task * 4; }
    else          { row = 32 + (lane >> 3);  xb = (lane & 7) * 4; }
}

// ---------------- the persistent kernel ----------------
__global__ void __launch_bounds__(TPB, 4)
k_crf(const float* __restrict__ img, const float4* __restrict__ unary,
      float4* __restrict__ dout, int nb) {
    extern __shared__ char dsm[];
    u64*   sIn  = (u64*)(dsm + OFF_IN0);
    float* sg   = (float*)(dsm + OFF_GRAY);
    u64*   sInB = (u64*)(dsm + OFF_INB);
    u64*   aH0  = (u64*)(dsm + OFF_AH0);
    u64*   aH1  = (u64*)(dsm + OFF_AH1);
    u64*   aH2  = (u64*)(dsm + OFF_AH2);
    u64*   bH0  = (u64*)(dsm + OFF_BH0);
    u64*   bH1  = (u64*)(dsm + OFF_BH1);
    u64*   sV   = (u64*)(dsm + OFF_SV);

    const int tid  = threadIdx.x;
    const int wid  = tid >> 5;
    const int lane = tid & 31;
    const int gid  = blockIdx.x * TPB + tid;
    const int T    = nb * TPB;

    unsigned gen;
    {
        __shared__ unsigned sgen;
        if (tid == 0) sgen = *(volatile unsigned*)&g_gen;
        __syncthreads();
        gen = sgen;
    }

    // ---- P0: grayscale + Q0 = softmax(-unary) ----
    for (int i = gid; i < NPIX; i += T) {
        float r = img[3 * i], gg = img[3 * i + 1], b = img[3 * i + 2];
        g_gray[i] = 0.2989f * r + 0.5870f * gg + 0.1140f * b;
        float4 u = unary[i];
        float4 q = softmax4(make_float4(-u.x, -u.y, -u.z, -u.w));
        g_Qxy[i] = pk2(q.x, q.y);
        g_Qzw[i] = pk2(q.z, q.w);
    }
    gen = gridbar(gen, nb);

    // ---- PreA: conv2D of (gray, gray^2) -> mI, iv, (a1,b1) ----
    for (int t = blockIdx.x; t < NTILES; t += nb) {
        int X0 = (t & (NTX - 1)) * TSX, Y0 = (t >> 4) * TSY;
        for (int s = tid; s < NELEM; s += TPB) {
            int r = s / SINP, c = s - r * SINP;
            int gx = X0 + c - RAD, gy = Y0 + r - RAD;
            u64 v = 0ULL;
            if (c < TINX && (unsigned)gx < WID && (unsigned)gy < HEI) {
                float gv = g_gray[gy * WID + gx];
                v = pk2(gv, gv * gv);
            }
            sIn[s] = v;
        }
        __syncthreads();
        for (int task = wid; task < 9; task += 8) {
            int row, xb; htask_geom(task, lane, row, xb);
            u64 a[4] = {0,0,0,0};
            const u64* rw = sIn + row * SINP + xb;
#pragma unroll
            for (int tt = 0; tt < 24; tt++) {
                u64 v = rw[tt];
#pragma unroll
                for (int m = 0; m < 4; m++) {
                    int w = tt - m;
                    if (w >= 0 && w < KS) fma2(a[m], v, wpc(wD(w)));
                }
            }
#pragma unroll
            for (int m = 0; m < 4; m++) aH0[row * SHP + xb + m] = a[m];
        }
        __syncthreads();
        if (wid < 4) {
            int py0 = wid * 4;
            u64 A[4] = {0,0,0,0};
#pragma unroll
            for (int j = 0; j < 24; j++) {
                u64 v = aH0[(py0 + j) * SHP + lane];
#pragma unroll
                for (int m = 0; m < 4; m++) {
                    int w = j - m;
                    if (w >= 0 && w < KS) fma2(A[m], v, wpc(wD(w)));
                }
            }
            float hdx = hsD(X0 + lane);
#pragma unroll
            for (int m = 0; m < 4; m++) {
                int py = py0 + m, gy = Y0 + py, idx = gy * WID + X0 + lane;
                float2 c = up2(A[m]);
                float g = up2(sIn[(py + RAD) * SINP + lane + RAD]).x;
                float mI  = (c.x - g) * SDINV_F;
                float mII = (c.y - g * g) * SDINV_F;
                float mp1 = (hdx * hsD(gy) - 1.f) * SDINV_F;
                float var = mII - mI * mI;
                float iv  = 1.f / (var + 1e-4f);
                float a1  = mI * (1.f - mp1) * iv;
                float b1  = mp1 - a1 * mI;
                g_mI[idx] = mI; g_iv[idx] = iv; g_ab1[idx] = pk2(a1, b1);
            }
        }
        __syncthreads();
    }
    gen = gridbar(gen, nb);

    // ---- PreB: conv2D of (a1,b1) -> ibn, spc ----
    for (int t = blockIdx.x; t < NTILES; t += nb) {
        int X0 = (t & (NTX - 1)) * TSX, Y0 = (t >> 4) * TSY;
        load_tile(sIn, g_ab1, X0, Y0, tid);
        __syncthreads();
        for (int task = wid; task < 9; task += 8) {
            int row, xb; htask_geom(task, lane, row, xb);
            u64 a[4] = {0,0,0,0};
            const u64* rw = sIn + row * SINP + xb;
#pragma unroll
            for (int tt = 0; tt < 24; tt++) {
                u64 v = rw[tt];
#pragma unroll
                for (int m = 0; m < 4; m++) {
                    int w = tt - m;
                    if (w >= 0 && w < KS) fma2(a[m], v, wpc(wD(w)));
                }
            }
#pragma unroll
            for (int m = 0; m < 4; m++) aH0[row * SHP + xb + m] = a[m];
        }
        __syncthreads();
        if (wid < 4) {
            int py0 = wid * 4;
            u64 A[4] = {0,0,0,0};
#pragma unroll
            for (int j = 0; j < 24; j++) {
                u64 v = aH0[(py0 + j) * SHP + lane];
#pragma unroll
                for (int m = 0; m < 4; m++) {
                    int w = j - m;
                    if (w >= 0 && w < KS) fma2(A[m], v, wpc(wD(w)));
                }
            }
            float hgx = hsG(X0 + lane);
#pragma unroll
            for (int m = 0; m < 4; m++) {
                int py = py0 + m, gy = Y0 + py, idx = gy * WID + X0 + lane;
                float2 c  = up2(A[m]);
                float2 ab = up2(sIn[(py + RAD) * SINP + lane + RAD]);
                float g = g_gray[idx];
                float gfa = (c.x - ab.x) * SDINV_F;
                float gfb = (c.y - ab.y) * SDINV_F;
                g_ibn[idx] = 10.f / (gfa * g + gfb);
                g_spc[idx] = 3.f / (hgx * hsG(gy) - 1.f);
            }
        }
        __syncthreads();
    }
    gen = gridbar(gen, nb);

    // ---- 5 mean-field iterations: 2 tiled phases each ----
    for (int it = 0; it < 5; it++) {
        // ===== PhaseA: conv2D(Q)x{G,D} + conv2D(grayQ)xD -> a,b,sp =====
        for (int t = blockIdx.x; t < NTILES; t += nb) {
            int X0 = (t & (NTX - 1)) * TSX, Y0 = (t >> 4) * TSY;
            for (int s = tid; s < NELEM; s += TPB) {
                int r = s / SINP, c = s - r * SINP;
                int gx = X0 + c - RAD, gy = Y0 + r - RAD;
                float v = 0.f;
                if (c < TINX && (unsigned)gx < WID && (unsigned)gy < HEI) v = g_gray[gy * WID + gx];
                sg[s] = v;
            }
            for (int h = 0; h < 2; h++) {
                load_tile(sIn, h ? g_Qzw : g_Qxy, X0, Y0, tid);
                __syncthreads();
                for (int task = wid; task < 9; task += 8) {
                    int row, xb; htask_geom(task, lane, row, xb);
                    u64 aD[4] = {0,0,0,0}, aG[4] = {0,0,0,0}, aI[4] = {0,0,0,0};
                    const u64*  rw = sIn + row * SINP + xb;
                    const float* rg = sg + row * SINP + xb;
#pragma unroll
                    for (int tt = 0; tt < 24; tt++) {
                        u64 v = rw[tt];
                        float gf = rg[tt];
                        u64 wv = mul2(v, pk2(gf, gf));
#pragma unroll
                        for (int m = 0; m < 4; m++) {
                            int w = tt - m;
                            if (w >= 0 && w < KS) {
                                fma2(aD[m], v,  wpc(wD(w)));
                                fma2(aG[m], v,  wpc(wG(w)));
                                fma2(aI[m], wv, wpc(wD(w)));
                            }
                        }
                    }
#pragma unroll
                    for (int m = 0; m < 4; m++) {
                        aH0[row * SHP + xb + m] = aD[m];
                        aH1[row * SHP + xb + m] = aG[m];
                        aH2[row * SHP + xb + m] = aI[m];
                    }
                }
                __syncthreads();
                // --- split V: warps 0-3 do D+G; warps 4-7 do I -> sV ---
                int py0 = (wid & 3) * 4;
                u64 AD[4] = {0,0,0,0}, AG[4] = {0,0,0,0};
                if (wid < 4) {
#pragma unroll
                    for (int j = 0; j < 24; j++) {
                        u64 v0 = aH0[(py0 + j) * SHP + lane];
                        u64 v1 = aH1[(py0 + j) * SHP + lane];
#pragma unroll
                        for (int m = 0; m < 4; m++) {
                            int w = j - m;
                            if (w >= 0 && w < KS) {
                                fma2(AD[m], v0, wpc(wD(w)));
                                fma2(AG[m], v1, wpc(wG(w)));
                            }
                        }
                    }
                } else {
                    u64 AI[4] = {0,0,0,0};
#pragma unroll
                    for (int j = 0; j < 24; j++) {
                        u64 v2 = aH2[(py0 + j) * SHP + lane];
#pragma unroll
                        for (int m = 0; m < 4; m++) {
                            int w = j - m;
                            if (w >= 0 && w < KS) fma2(AI[m], v2, wpc(wD(w)));
                        }
                    }
#pragma unroll
                    for (int m = 0; m < 4; m++) sV[(py0 + m) * SVP + lane] = AI[m];
                }
                __syncthreads();
                if (wid < 4) {
#pragma unroll
                    for (int m = 0; m < 4; m++) {
                        int py = py0 + m, idx = (Y0 + py) * WID + X0 + lane;
                        float2 q = up2(sIn[(py + RAD) * SINP + lane + RAD]);
                        float g = sg[(py + RAD) * SINP + lane + RAD];
                        float2 ad = up2(AD[m]), ag = up2(AG[m]);
                        float2 ai = up2(sV[py * SVP + lane]);
                        float mI = g_mI[idx], iv = g_iv[idx], spc = g_spc[idx];
                        float spx = (ag.x - q.x) * spc,         spy = (ag.y - q.y) * spc;
                        float mpx = (ad.x - q.x) * SDINV_F,     mpy = (ad.y - q.y) * SDINV_F;
                        float mix = (ai.x - g * q.x) * SDINV_F, miy = (ai.y - g * q.y) * SDINV_F;
                        float ax = (mix - mI * mpx) * iv,       ay = (miy - mI * mpy) * iv;
                        float bx = mpx - ax * mI,               by = mpy - ay * mI;
                        if (h == 0) {
                            g_a0[idx]  = pk2(ax, ay);
                            g_b0[idx]  = pk2(bx, by);
                            g_sp0[idx] = pk2(spx, spy);
                        } else {
                            g_a1p[idx] = pk2(ax, ay);
                            g_b1p[idx] = pk2(bx, by);
                            g_sp1[idx] = pk2(spx, spy);
                        }
                    }
                }
                __syncthreads();
            }
        }
        gen = gridbar(gen, nb);

        // ===== PhaseB: conv2D(a,b) + message + softmax -> Q / dout =====
        for (int t = blockIdx.x; t < NTILES; t += nb) {
            int X0 = (t & (NTX - 1)) * TSX, Y0 = (t >> 4) * TSY;
            float z0[8];
            for (int h = 0; h < 2; h++) {
                load_tile(sIn,  h ? g_a1p : g_a0, X0, Y0, tid);
                load_tile(sInB, h ? g_b1p : g_b0, X0, Y0, tid);
                __syncthreads();
                for (int task = wid; task < 9; task += 8) {
                    int row, xb; htask_geom(task, lane, row, xb);
                    u64 aA[4] = {0,0,0,0}, aB[4] = {0,0,0,0};
                    const u64* rwA = sIn  + row * SINP + xb;
                    const u64* rwB = sInB + row * SINP + xb;
#pragma unroll
                    for (int tt = 0; tt < 24; tt++) {
                        u64 vA = rwA[tt], vB = rwB[tt];
#pragma unroll
                        for (int m = 0; m < 4; m++) {
                            int w = tt - m;
                            if (w >= 0 && w < KS) {
                                fma2(aA[m], vA, wpc(wD(w)));
                                fma2(aB[m], vB, wpc(wD(w)));
                            }
                        }
                    }
#pragma unroll
                    for (int m = 0; m < 4; m++) {
                        bH0[row * SHP + xb + m] = aA[m];
                        bH1[row * SHP + xb + m] = aB[m];
                    }
                }
                __syncthreads();
                // --- split V: warps 0-3 do A; warps 4-7 do B -> sV ---
                int py0 = (wid & 3) * 4;
                u64 AA[4] = {0,0,0,0};
                if (wid < 4) {
#pragma unroll
                    for (int j = 0; j < 24; j++) {
                        u64 v0 = bH0[(py0 + j) * SHP + lane];
#pragma unroll
                        for (int m = 0; m < 4; m++) {
                            int w = j - m;
                            if (w >= 0 && w < KS) fma2(AA[m], v0, wpc(wD(w)));
                        }
                    }
                } else {
                    u64 AB[4] = {0,0,0,0};
#pragma unroll
                    for (int j = 0; j < 24; j++) {
                        u64 v1 = bH1[(py0 + j) * SHP + lane];
#pragma unroll
                        for (int m = 0; m < 4; m++) {
                            int w = j - m;
                            if (w >= 0 && w < KS) fma2(AB[m], v1, wpc(wD(w)));
                        }
                    }
#pragma unroll
                    for (int m = 0; m < 4; m++) sV[(py0 + m) * SVP + lane] = AB[m];
                }
                __syncthreads();
                if (wid < 4) {
#pragma unroll
                    for (int m = 0; m < 4; m++) {
                        int py = py0 + m, idx = (Y0 + py) * WID + X0 + lane;
                        float2 ac = up2(sIn [(py + RAD) * SINP + lane + RAD]);
                        float2 bc = up2(sInB[(py + RAD) * SINP + lane + RAD]);
                        float2 aa = up2(AA[m]);
                        float2 ab = up2(sV[py * SVP + lane]);
                        float2 sp = up2(h ? g_sp1[idx] : g_sp0[idx]);
                        float ibn = g_ibn[idx], g = g_gray[idx];
                        float2 uu = *((const float2*)unary + 2 * idx + h);
                        float zx = sp.x + ((aa.x - ac.x) * SDINV_F * g
                                         + (ab.x - bc.x) * SDINV_F) * ibn - uu.x;
                        float zy = sp.y + ((aa.y - ac.y) * SDINV_F * g
                                         + (ab.y - bc.y) * SDINV_F) * ibn - uu.y;
                        if (h == 0) {
                            z0[2*m] = zx; z0[2*m+1] = zy;
                        } else {
                            float4 q = softmax4(make_float4(z0[2*m], z0[2*m+1], zx, zy));
                            if (it == 4) {
                                dout[idx] = q;
                            } else {
                                g_Qxy[idx] = pk2(q.x, q.y);
                                g_Qzw[idx] = pk2(q.z, q.w);
                            }
                        }
                    }
                }
                __syncthreads();
            }
        }
        if (it < 4) gen = gridbar(gen, nb);
    }
}

// ---------------- launch ----------------
extern "C" void kernel_launch(void* const* d_in, const int* in_sizes, int n_in,
                              void* d_out, int out_size) {
    const float* unary = nullptr;
    const float* image = nullptr;
    for (int i = 0; i < n_in; i++) {
        if (in_sizes[i] == NPIX * 4) unary = (const float*)d_in[i];
        else if (in_sizes[i] == NPIX * 3) image = (const float*)d_in[i];
    }

    cudaFuncSetAttribute(k_crf, cudaFuncAttributeMaxDynamicSharedMemorySize, SMEM_BYTES);

    int sms = 0, occ = 0;
    cudaDeviceGetAttribute(&sms, cudaDevAttrMultiProcessorCount, 0);
    cudaOccupancyMaxActiveBlocksPerMultiprocessor(&occ, k_crf, TPB, SMEM_BYTES);
    if (sms <= 0) sms = 148;
    if (occ <= 0) occ = 1;
    int nb = sms * occ;
    if (nb > 1024) nb = 1024;

    k_crf<<<nb, TPB, SMEM_BYTES>>>(image, (const float4*)unary, (float4*)d_out, nb);
}